// round 1
// baseline (speedup 1.0000x reference)
#include <cuda_runtime.h>

// Problem constants
#define BDIM 32
#define SDIM 2048
#define HDIM 1024
#define RDIM (BDIM * SDIM)   // 65536 rows

// GEMM tiling
#define BM 128
#define BN 128
#define BK 16
#define LDA 132              // padded smem row stride (floats)

// Scratch (device globals; no allocation allowed)
__device__ float g_bias[BDIM * HDIM];     // h_proj + b_attn, per (b, o)
__device__ float g_logits[RDIM];          // pre-softmax attention logits

// ---------------------------------------------------------------------------
// Packed f32x2 helpers (Blackwell FFMA2 path)
// ---------------------------------------------------------------------------
__device__ __forceinline__ unsigned long long pack2(float x, float y) {
    unsigned long long r;
    asm("mov.b64 %0, {%1, %2};" : "=l"(r) : "f"(x), "f"(y));
    return r;
}
__device__ __forceinline__ void unpack2(float& x, float& y, unsigned long long p) {
    asm("mov.b64 {%0, %1}, %2;" : "=f"(x), "=f"(y) : "l"(p));
}
__device__ __forceinline__ void fma2(unsigned long long& d,
                                     unsigned long long a,
                                     unsigned long long b) {
    asm("fma.rn.f32x2 %0, %1, %2, %0;" : "+l"(d) : "l"(a), "l"(b));
}

// ---------------------------------------------------------------------------
// Kernel A: bias[b][o] = sum_h hidden[b][h] * W[o][h] + b_attn[o]
//           (Wh = first H columns of W_attn rows; W row-major (H, 2H))
// grid (B, H/128), block 128
// ---------------------------------------------------------------------------
__global__ void bias_kernel(const float* __restrict__ hidden,
                            const float* __restrict__ W,
                            const float* __restrict__ b_attn) {
    __shared__ float4 sh[HDIM / 4];
    const int b   = blockIdx.x;
    const int tid = threadIdx.x;

    const float4* hv = (const float4*)(hidden + (size_t)b * HDIM);
    for (int i = tid; i < HDIM / 4; i += 128) sh[i] = hv[i];
    __syncthreads();

    const int o = blockIdx.y * 128 + tid;
    const float4* wrow = (const float4*)(W + (size_t)o * (2 * HDIM));
    float acc = b_attn[o];
#pragma unroll 8
    for (int i = 0; i < HDIM / 4; i++) {
        const float4 w  = wrow[i];
        const float4 h4 = sh[i];
        acc = fmaf(w.x, h4.x, acc);
        acc = fmaf(w.y, h4.y, acc);
        acc = fmaf(w.z, h4.z, acc);
        acc = fmaf(w.w, h4.w, acc);
    }
    g_bias[b * HDIM + o] = acc;
}

// ---------------------------------------------------------------------------
// Kernel B: fused GEMM + tanh + dot(v) -> logits
//   For each row r (=b*S+s): logit[r] = sum_o v[o] * tanh( enc[r,:]·We[o,:] + bias[b,o] )
//   We[o][k] = W[o*2H + H + k]
// Block: 256 threads (16x16), thread tile 8x8, tiles BM=BN=128, BK=16.
// Each block owns BM rows and loops over all H/BN o-tiles, so the per-row
// tanh·v partial sums stay in registers; logits written once per row.
// grid RDIM/BM = 512
// ---------------------------------------------------------------------------
__global__ void __launch_bounds__(256, 2)
fused_attn_kernel(const float* __restrict__ enc,
                  const float* __restrict__ W,
                  const float* __restrict__ v) {
    __shared__ float As[BK][LDA];   // enc tile, transposed: As[k][m]
    __shared__ float Bs[BK][LDA];   // We tile,  transposed: Bs[k][n]
    __shared__ float s_row[BM];

    const int tid = threadIdx.x;
    const int tx  = tid & 15;       // col-group 0..15
    const int ty  = tid >> 4;       // row-group 0..15
    const int r0  = blockIdx.x * BM;
    const int b   = r0 >> 11;       // r0 / SDIM (SDIM=2048)

    if (tid < BM) s_row[tid] = 0.0f;

    float part[8];
#pragma unroll
    for (int i = 0; i < 8; i++) part[i] = 0.0f;

    const float* bias = g_bias + (size_t)b * HDIM;

    for (int ot = 0; ot < HDIM / BN; ot++) {
        const int o0 = ot * BN;

        unsigned long long acc[4][8];   // [row-pair][col] ; lo=row 2*i2, hi=row 2*i2+1
#pragma unroll
        for (int i2 = 0; i2 < 4; i2++)
#pragma unroll
            for (int j = 0; j < 8; j++) acc[i2][j] = 0ull;

        for (int kt = 0; kt < HDIM / BK; kt++) {
            const int k0 = kt * BK;

            // Load enc tile (BM x BK), store transposed
#pragma unroll
            for (int l = 0; l < 2; l++) {
                const int idx = l * 256 + tid;
                const int row = idx >> 2;
                const int c4  = (idx & 3) * 4;
                const float4 w = *(const float4*)(enc + (size_t)(r0 + row) * HDIM + k0 + c4);
                As[c4 + 0][row] = w.x;
                As[c4 + 1][row] = w.y;
                As[c4 + 2][row] = w.z;
                As[c4 + 3][row] = w.w;
            }
            // Load We tile (BN x BK), store transposed
#pragma unroll
            for (int l = 0; l < 2; l++) {
                const int idx = l * 256 + tid;
                const int row = idx >> 2;
                const int c4  = (idx & 3) * 4;
                const float4 w = *(const float4*)(W + (size_t)(o0 + row) * (2 * HDIM) + HDIM + k0 + c4);
                Bs[c4 + 0][row] = w.x;
                Bs[c4 + 1][row] = w.y;
                Bs[c4 + 2][row] = w.z;
                Bs[c4 + 3][row] = w.w;
            }
            __syncthreads();

#pragma unroll
            for (int k = 0; k < BK; k++) {
                // a: 4 packed row-pairs (8 consecutive rows for this thread)
                const ulonglong2 aA = *(const ulonglong2*)&As[k][ty * 8];
                const ulonglong2 aB = *(const ulonglong2*)&As[k][ty * 8 + 4];
                unsigned long long aa[4];
                aa[0] = aA.x; aa[1] = aA.y; aa[2] = aB.x; aa[3] = aB.y;

                // b: 8 cols, duplicated into pairs
                const float4 b0 = *(const float4*)&Bs[k][tx * 8];
                const float4 b1 = *(const float4*)&Bs[k][tx * 8 + 4];
                unsigned long long bb[8];
                bb[0] = pack2(b0.x, b0.x);
                bb[1] = pack2(b0.y, b0.y);
                bb[2] = pack2(b0.z, b0.z);
                bb[3] = pack2(b0.w, b0.w);
                bb[4] = pack2(b1.x, b1.x);
                bb[5] = pack2(b1.y, b1.y);
                bb[6] = pack2(b1.z, b1.z);
                bb[7] = pack2(b1.w, b1.w);

#pragma unroll
                for (int i2 = 0; i2 < 4; i2++)
#pragma unroll
                    for (int j = 0; j < 8; j++)
                        fma2(acc[i2][j], aa[i2], bb[j]);
            }
            __syncthreads();
        }

        // Epilogue for this o-tile: tanh(acc + bias[o]) * v[o], accumulate per-row
#pragma unroll
        for (int j = 0; j < 8; j++) {
            const int o  = o0 + tx * 8 + j;
            const float bo = bias[o];
            const float vv = v[o];
#pragma unroll
            for (int i2 = 0; i2 < 4; i2++) {
                float c0, c1;
                unpack2(c0, c1, acc[i2][j]);
                part[2 * i2 + 0] += tanhf(c0 + bo) * vv;
                part[2 * i2 + 1] += tanhf(c1 + bo) * vv;
            }
        }
    }

    // Reduce partials across the 16 col-groups sharing each row
#pragma unroll
    for (int i = 0; i < 8; i++)
        atomicAdd(&s_row[ty * 8 + i], part[i]);
    __syncthreads();
    if (tid < BM) g_logits[r0 + tid] = s_row[tid];
}

// ---------------------------------------------------------------------------
// Kernel C: softmax over s per batch. grid B, block 256.
// ---------------------------------------------------------------------------
__global__ void softmax_kernel(float* __restrict__ out) {
    __shared__ float red[256];
    const int b   = blockIdx.x;
    const int tid = threadIdx.x;
    const float* lg = g_logits + (size_t)b * SDIM;

    float vals[SDIM / 256];
    float lmax = -1e30f;
#pragma unroll
    for (int i = 0; i < SDIM / 256; i++) {
        vals[i] = lg[tid + i * 256];
        lmax = fmaxf(lmax, vals[i]);
    }
    red[tid] = lmax;
    __syncthreads();
    for (int s = 128; s > 0; s >>= 1) {
        if (tid < s) red[tid] = fmaxf(red[tid], red[tid + s]);
        __syncthreads();
    }
    lmax = red[0];
    __syncthreads();

    float lsum = 0.0f;
#pragma unroll
    for (int i = 0; i < SDIM / 256; i++) {
        vals[i] = expf(vals[i] - lmax);
        lsum += vals[i];
    }
    red[tid] = lsum;
    __syncthreads();
    for (int s = 128; s > 0; s >>= 1) {
        if (tid < s) red[tid] += red[tid + s];
        __syncthreads();
    }
    const float inv = 1.0f / red[0];
#pragma unroll
    for (int i = 0; i < SDIM / 256; i++)
        out[(size_t)b * SDIM + tid + i * 256] = vals[i] * inv;
}

// ---------------------------------------------------------------------------
// Launch: inputs (metadata order): hidden, encoder_outputs, W_attn, b_attn, v
// ---------------------------------------------------------------------------
extern "C" void kernel_launch(void* const* d_in, const int* in_sizes, int n_in,
                              void* d_out, int out_size) {
    const float* hidden = (const float*)d_in[0];
    const float* enc    = (const float*)d_in[1];
    const float* W      = (const float*)d_in[2];
    const float* b_attn = (const float*)d_in[3];
    const float* v      = (const float*)d_in[4];
    float* out = (float*)d_out;

    bias_kernel<<<dim3(BDIM, HDIM / 128), 128>>>(hidden, W, b_attn);
    fused_attn_kernel<<<RDIM / BM, 256>>>(enc, W, v);
    softmax_kernel<<<BDIM, 256>>>(out);
}

// round 2
// speedup vs baseline: 1.0001x; 1.0001x over previous
#include <cuda_runtime.h>

// Problem constants
#define BDIM 32
#define SDIM 2048
#define HDIM 1024
#define RDIM (BDIM * SDIM)   // 65536 rows

// GEMM tiling
#define BM 128
#define BN 128
#define BK 16
#define LDA 132              // padded smem row stride (floats)

// Scratch (device globals; no allocation allowed)
__device__ float g_bias[BDIM * HDIM];     // h_proj + b_attn, per (b, o)
__device__ float g_logits[RDIM];          // pre-softmax attention logits

// ---------------------------------------------------------------------------
// Packed f32x2 helpers (Blackwell FFMA2 path)
// ---------------------------------------------------------------------------
__device__ __forceinline__ unsigned long long pack2(float x, float y) {
    unsigned long long r;
    asm("mov.b64 %0, {%1, %2};" : "=l"(r) : "f"(x), "f"(y));
    return r;
}
__device__ __forceinline__ void unpack2(float& x, float& y, unsigned long long p) {
    asm("mov.b64 {%0, %1}, %2;" : "=f"(x), "=f"(y) : "l"(p));
}
__device__ __forceinline__ void fma2(unsigned long long& d,
                                     unsigned long long a,
                                     unsigned long long b) {
    asm("fma.rn.f32x2 %0, %1, %2, %0;" : "+l"(d) : "l"(a), "l"(b));
}

// ---------------------------------------------------------------------------
// Kernel A: bias[b][o] = sum_h hidden[b][h] * W[o][h] + b_attn[o]
//           (Wh = first H columns of W_attn rows; W row-major (H, 2H))
// grid (B, H/128), block 128
// ---------------------------------------------------------------------------
__global__ void bias_kernel(const float* __restrict__ hidden,
                            const float* __restrict__ W,
                            const float* __restrict__ b_attn) {
    __shared__ float4 sh[HDIM / 4];
    const int b   = blockIdx.x;
    const int tid = threadIdx.x;

    const float4* hv = (const float4*)(hidden + (size_t)b * HDIM);
    for (int i = tid; i < HDIM / 4; i += 128) sh[i] = hv[i];
    __syncthreads();

    const int o = blockIdx.y * 128 + tid;
    const float4* wrow = (const float4*)(W + (size_t)o * (2 * HDIM));
    float acc = b_attn[o];
#pragma unroll 8
    for (int i = 0; i < HDIM / 4; i++) {
        const float4 w  = wrow[i];
        const float4 h4 = sh[i];
        acc = fmaf(w.x, h4.x, acc);
        acc = fmaf(w.y, h4.y, acc);
        acc = fmaf(w.z, h4.z, acc);
        acc = fmaf(w.w, h4.w, acc);
    }
    g_bias[b * HDIM + o] = acc;
}

// ---------------------------------------------------------------------------
// Kernel B: fused GEMM + tanh + dot(v) -> logits
//   For each row r (=b*S+s): logit[r] = sum_o v[o] * tanh( enc[r,:]·We[o,:] + bias[b,o] )
//   We[o][k] = W[o*2H + H + k]
// Block: 256 threads (16x16), thread tile 8x8, tiles BM=BN=128, BK=16.
// Each block owns BM rows and loops over all H/BN o-tiles, so the per-row
// tanh·v partial sums stay in registers; logits written once per row.
// grid RDIM/BM = 512
// ---------------------------------------------------------------------------
__global__ void __launch_bounds__(256, 2)
fused_attn_kernel(const float* __restrict__ enc,
                  const float* __restrict__ W,
                  const float* __restrict__ v) {
    __shared__ float As[BK][LDA];   // enc tile, transposed: As[k][m]
    __shared__ float Bs[BK][LDA];   // We tile,  transposed: Bs[k][n]
    __shared__ float s_row[BM];

    const int tid = threadIdx.x;
    const int tx  = tid & 15;       // col-group 0..15
    const int ty  = tid >> 4;       // row-group 0..15
    const int r0  = blockIdx.x * BM;
    const int b   = r0 >> 11;       // r0 / SDIM (SDIM=2048)

    if (tid < BM) s_row[tid] = 0.0f;

    float part[8];
#pragma unroll
    for (int i = 0; i < 8; i++) part[i] = 0.0f;

    const float* bias = g_bias + (size_t)b * HDIM;

    for (int ot = 0; ot < HDIM / BN; ot++) {
        const int o0 = ot * BN;

        unsigned long long acc[4][8];   // [row-pair][col] ; lo=row 2*i2, hi=row 2*i2+1
#pragma unroll
        for (int i2 = 0; i2 < 4; i2++)
#pragma unroll
            for (int j = 0; j < 8; j++) acc[i2][j] = 0ull;

        for (int kt = 0; kt < HDIM / BK; kt++) {
            const int k0 = kt * BK;

            // Load enc tile (BM x BK), store transposed
#pragma unroll
            for (int l = 0; l < 2; l++) {
                const int idx = l * 256 + tid;
                const int row = idx >> 2;
                const int c4  = (idx & 3) * 4;
                const float4 w = *(const float4*)(enc + (size_t)(r0 + row) * HDIM + k0 + c4);
                As[c4 + 0][row] = w.x;
                As[c4 + 1][row] = w.y;
                As[c4 + 2][row] = w.z;
                As[c4 + 3][row] = w.w;
            }
            // Load We tile (BN x BK), store transposed
#pragma unroll
            for (int l = 0; l < 2; l++) {
                const int idx = l * 256 + tid;
                const int row = idx >> 2;
                const int c4  = (idx & 3) * 4;
                const float4 w = *(const float4*)(W + (size_t)(o0 + row) * (2 * HDIM) + HDIM + k0 + c4);
                Bs[c4 + 0][row] = w.x;
                Bs[c4 + 1][row] = w.y;
                Bs[c4 + 2][row] = w.z;
                Bs[c4 + 3][row] = w.w;
            }
            __syncthreads();

#pragma unroll
            for (int k = 0; k < BK; k++) {
                // a: 4 packed row-pairs (8 consecutive rows for this thread)
                const ulonglong2 aA = *(const ulonglong2*)&As[k][ty * 8];
                const ulonglong2 aB = *(const ulonglong2*)&As[k][ty * 8 + 4];
                unsigned long long aa[4];
                aa[0] = aA.x; aa[1] = aA.y; aa[2] = aB.x; aa[3] = aB.y;

                // b: 8 cols, duplicated into pairs
                const float4 b0 = *(const float4*)&Bs[k][tx * 8];
                const float4 b1 = *(const float4*)&Bs[k][tx * 8 + 4];
                unsigned long long bb[8];
                bb[0] = pack2(b0.x, b0.x);
                bb[1] = pack2(b0.y, b0.y);
                bb[2] = pack2(b0.z, b0.z);
                bb[3] = pack2(b0.w, b0.w);
                bb[4] = pack2(b1.x, b1.x);
                bb[5] = pack2(b1.y, b1.y);
                bb[6] = pack2(b1.z, b1.z);
                bb[7] = pack2(b1.w, b1.w);

#pragma unroll
                for (int i2 = 0; i2 < 4; i2++)
#pragma unroll
                    for (int j = 0; j < 8; j++)
                        fma2(acc[i2][j], aa[i2], bb[j]);
            }
            __syncthreads();
        }

        // Epilogue for this o-tile: tanh(acc + bias[o]) * v[o], accumulate per-row
#pragma unroll
        for (int j = 0; j < 8; j++) {
            const int o  = o0 + tx * 8 + j;
            const float bo = bias[o];
            const float vv = v[o];
#pragma unroll
            for (int i2 = 0; i2 < 4; i2++) {
                float c0, c1;
                unpack2(c0, c1, acc[i2][j]);
                part[2 * i2 + 0] += tanhf(c0 + bo) * vv;
                part[2 * i2 + 1] += tanhf(c1 + bo) * vv;
            }
        }
    }

    // Reduce partials across the 16 col-groups sharing each row
#pragma unroll
    for (int i = 0; i < 8; i++)
        atomicAdd(&s_row[ty * 8 + i], part[i]);
    __syncthreads();
    if (tid < BM) g_logits[r0 + tid] = s_row[tid];
}

// ---------------------------------------------------------------------------
// Kernel C: softmax over s per batch. grid B, block 256.
// ---------------------------------------------------------------------------
__global__ void softmax_kernel(float* __restrict__ out) {
    __shared__ float red[256];
    const int b   = blockIdx.x;
    const int tid = threadIdx.x;
    const float* lg = g_logits + (size_t)b * SDIM;

    float vals[SDIM / 256];
    float lmax = -1e30f;
#pragma unroll
    for (int i = 0; i < SDIM / 256; i++) {
        vals[i] = lg[tid + i * 256];
        lmax = fmaxf(lmax, vals[i]);
    }
    red[tid] = lmax;
    __syncthreads();
    for (int s = 128; s > 0; s >>= 1) {
        if (tid < s) red[tid] = fmaxf(red[tid], red[tid + s]);
        __syncthreads();
    }
    lmax = red[0];
    __syncthreads();

    float lsum = 0.0f;
#pragma unroll
    for (int i = 0; i < SDIM / 256; i++) {
        vals[i] = expf(vals[i] - lmax);
        lsum += vals[i];
    }
    red[tid] = lsum;
    __syncthreads();
    for (int s = 128; s > 0; s >>= 1) {
        if (tid < s) red[tid] += red[tid + s];
        __syncthreads();
    }
    const float inv = 1.0f / red[0];
#pragma unroll
    for (int i = 0; i < SDIM / 256; i++)
        out[(size_t)b * SDIM + tid + i * 256] = vals[i] * inv;
}

// ---------------------------------------------------------------------------
// Launch: inputs (metadata order): hidden, encoder_outputs, W_attn, b_attn, v
// ---------------------------------------------------------------------------
extern "C" void kernel_launch(void* const* d_in, const int* in_sizes, int n_in,
                              void* d_out, int out_size) {
    const float* hidden = (const float*)d_in[0];
    const float* enc    = (const float*)d_in[1];
    const float* W      = (const float*)d_in[2];
    const float* b_attn = (const float*)d_in[3];
    const float* v      = (const float*)d_in[4];
    float* out = (float*)d_out;

    bias_kernel<<<dim3(BDIM, HDIM / 128), 128>>>(hidden, W, b_attn);
    fused_attn_kernel<<<RDIM / BM, 256>>>(enc, W, v);
    softmax_kernel<<<BDIM, 256>>>(out);
}

// round 6
// speedup vs baseline: 2.2175x; 2.2173x over previous
#include <cuda_runtime.h>
#include <cuda_bf16.h>
#include <cstdint>

#define SDIM 2048
#define HDIM 1024
#define RDIM 65536

// ---- gemm tiling ----
#define ROWS_CTA 128
#define NT 256                 // o-cols per iter
#define OITERS 4
#define BK 32
#define GSTEPS (OITERS * 32)   // 128 k32-steps total

// ---- smem layout (bytes). 80B padded rows (64B data + 16B pad) ----
#define STRIDE 80
#define SA 0                   // A_hi @0 (10240), A_lo @10240
#define SB 20480               // B_hi @20480 (20480), B_lo @40960
#define STAGE_SZ 61440
#define SM_BIAS (2 * STAGE_SZ) // 122880
#define SM_V    (SM_BIAS + 4096)
#define SM_ROW  (SM_V + 4096)
#define SMEM_TOTAL (SM_ROW + 512)   // 131584

__device__ __align__(16) __nv_bfloat16 g_enc_hi[(size_t)RDIM * HDIM]; // 128MB
__device__ __align__(16) __nv_bfloat16 g_enc_lo[(size_t)RDIM * HDIM]; // 128MB
__device__ __align__(16) __nv_bfloat16 g_we_hi[(size_t)HDIM * HDIM];  // 2MB
__device__ __align__(16) __nv_bfloat16 g_we_lo[(size_t)HDIM * HDIM];  // 2MB
__device__ float g_bias[32 * HDIM];
__device__ float g_logits[RDIM];

// ---------------- helpers ----------------
__device__ __forceinline__ uint32_t smem_u32(const void* p) {
    uint32_t a;
    asm("{ .reg .u64 t; cvta.to.shared.u64 t, %1; cvt.u32.u64 %0, t; }" : "=r"(a) : "l"(p));
    return a;
}
__device__ __forceinline__ void cp16(uint32_t dst, const void* src) {
    asm volatile("cp.async.cg.shared.global [%0], [%1], 16;" :: "r"(dst), "l"(src) : "memory");
}
__device__ __forceinline__ void ldsm4(uint32_t* r, uint32_t a) {
    asm volatile("ldmatrix.sync.aligned.m8n8.x4.shared.b16 {%0,%1,%2,%3}, [%4];"
                 : "=r"(r[0]), "=r"(r[1]), "=r"(r[2]), "=r"(r[3]) : "r"(a));
}
__device__ __forceinline__ void mma16816(float* c, const uint32_t* a, const uint32_t* b) {
    asm volatile("mma.sync.aligned.m16n8k16.row.col.f32.bf16.bf16.f32 "
                 "{%0,%1,%2,%3}, {%4,%5,%6,%7}, {%8,%9}, {%0,%1,%2,%3};"
                 : "+f"(c[0]), "+f"(c[1]), "+f"(c[2]), "+f"(c[3])
                 : "r"(a[0]), "r"(a[1]), "r"(a[2]), "r"(a[3]), "r"(b[0]), "r"(b[1]));
}
// accurate fast tanh: sign(x)*(1 - 2/(e^{2|x|}+1)), 2 MUFU, ~1e-6 err
__device__ __forceinline__ float ftanh(float x) {
    float ax = fminf(fabsf(x), 12.0f);
    float e;
    asm("ex2.approx.f32 %0, %1;" : "=f"(e) : "f"(ax * 2.885390082f));
    float r;
    asm("rcp.approx.f32 %0, %1;" : "=f"(r) : "f"(e + 1.0f));
    return copysignf(fmaf(-2.0f, r, 1.0f), x);
}
__device__ __forceinline__ void split8(const float* f, __nv_bfloat16* hi, __nv_bfloat16* lo) {
#pragma unroll
    for (int i = 0; i < 8; i++) {
        hi[i] = __float2bfloat16_rn(f[i]);
        lo[i] = __float2bfloat16_rn(f[i] - __bfloat162float(hi[i]));
    }
}

// ---------------- prep: enc + We -> bf16 hi/lo, bias GEMV ----------------
// blocks: [0,32768) enc, [32768,33280) We, [33280,33408) bias
__global__ void __launch_bounds__(256) prep_kernel(const float* __restrict__ enc,
                                                   const float* __restrict__ W,
                                                   const float* __restrict__ hidden,
                                                   const float* __restrict__ b_attn) {
    __shared__ float4 sh[HDIM / 4];
    const int bid = blockIdx.x, tid = threadIdx.x;
    if (bid < 32768) {
        const size_t base = ((size_t)bid * 256 + tid) * 8;
        const float4* p = (const float4*)(enc + base);
        const float4 a = p[0], b = p[1];
        const float f[8] = {a.x, a.y, a.z, a.w, b.x, b.y, b.z, b.w};
        __nv_bfloat16 hi[8], lo[8];
        split8(f, hi, lo);
        *(uint4*)(g_enc_hi + base) = *(const uint4*)hi;
        *(uint4*)(g_enc_lo + base) = *(const uint4*)lo;
    } else if (bid < 33280) {
        const size_t base = ((size_t)(bid - 32768) * 256 + tid) * 8;
        const int o = (int)(base >> 10), k = (int)(base & 1023);
        const float4* p = (const float4*)(W + (size_t)o * 2 * HDIM + HDIM + k);
        const float4 a = p[0], b = p[1];
        const float f[8] = {a.x, a.y, a.z, a.w, b.x, b.y, b.z, b.w};
        __nv_bfloat16 hi[8], lo[8];
        split8(f, hi, lo);
        *(uint4*)(g_we_hi + base) = *(const uint4*)hi;
        *(uint4*)(g_we_lo + base) = *(const uint4*)lo;
    } else {
        const int b2 = bid - 33280;        // 0..127
        const int b = b2 & 31, ot = b2 >> 5;
        const float4* hv = (const float4*)(hidden + (size_t)b * HDIM);
        for (int i = tid; i < HDIM / 4; i += 256) sh[i] = hv[i];
        __syncthreads();
        const int o = ot * 256 + tid;
        const float4* wr = (const float4*)(W + (size_t)o * 2 * HDIM);
        float acc = b_attn[o];
#pragma unroll 8
        for (int i = 0; i < HDIM / 4; i++) {
            const float4 w = wr[i], h4 = sh[i];
            acc = fmaf(w.x, h4.x, acc);
            acc = fmaf(w.y, h4.y, acc);
            acc = fmaf(w.z, h4.z, acc);
            acc = fmaf(w.w, h4.w, acc);
        }
        g_bias[b * HDIM + o] = acc;
    }
}

// ---------------- gemm: mma.sync bf16 3-term split + fused tanh·v ----------------
__device__ __forceinline__ void load_stage(uint32_t sb, int gs, int r0) {
    const int buf = gs & 1, k0 = (gs & 31) * 32, o0 = (gs >> 5) * NT;
    const int tid = threadIdx.x;
    const uint32_t base = sb + buf * STAGE_SZ;
    // A: 128 rows x 32 bf16 x {hi,lo}  (1024 x 16B chunks)
#pragma unroll
    for (int i = 0; i < 4; i++) {
        const int c = tid + i * 256;
        const int mat = c >> 9, rem = c & 511, row = rem >> 2, seg = rem & 3;
        const __nv_bfloat16* g = (mat ? g_enc_lo : g_enc_hi)
                               + (size_t)(r0 + row) * HDIM + k0 + seg * 8;
        cp16(base + SA + mat * 10240 + row * STRIDE + seg * 16, g);
    }
    // B: 256 rows x 32 bf16 x {hi,lo}  (2048 x 16B chunks)
#pragma unroll
    for (int i = 0; i < 8; i++) {
        const int c = tid + i * 256;
        const int mat = c >> 10, rem = c & 1023, row = rem >> 2, seg = rem & 3;
        const __nv_bfloat16* g = (mat ? g_we_lo : g_we_hi)
                               + (size_t)(o0 + row) * HDIM + k0 + seg * 8;
        cp16(base + SB + mat * 20480 + row * STRIDE + seg * 16, g);
    }
}

__global__ void __launch_bounds__(256, 1)
gemm_kernel(const float* __restrict__ v) {
    extern __shared__ char smem[];
    const uint32_t sb = smem_u32(smem);
    const int tid = threadIdx.x;
    const int lane = tid & 31, warp = tid >> 5;
    const int warp_m = (warp >> 1) * 32;      // 4 warps over M
    const int warp_n = (warp & 1) * 128;      // 2 warps over N
    const int r0 = blockIdx.x * ROWS_CTA;
    const int bb = r0 >> 11;

    float* s_bias = (float*)(smem + SM_BIAS);
    float* s_v    = (float*)(smem + SM_V);
    float* s_row  = (float*)(smem + SM_ROW);
    for (int i = tid; i < HDIM; i += 256) {
        s_bias[i] = g_bias[bb * HDIM + i];
        s_v[i] = v[i];
    }
    if (tid < ROWS_CTA) s_row[tid] = 0.0f;

    // ldmatrix per-lane address components
    const int q = lane >> 3, rr = lane & 7;
    const int a_row_off = (q & 1) * 8 + rr;       // + mt*16 + warp_m
    const int a_k_off   = (q >> 1) * 8;           // + kk
    const int b_row_off = (q >> 1) * 8 + rr;      // + p*16 (+ warp_n at addr build)
    const int b_k_off   = (q & 1) * 8;            // + kk

    load_stage(sb, 0, r0);
    asm volatile("cp.async.commit_group;" ::: "memory");

    float part[4] = {0.f, 0.f, 0.f, 0.f};
    float acc[2][16][4];

    for (int gs = 0; gs < GSTEPS; gs++) {
        const int buf = gs & 1;
        if (gs + 1 < GSTEPS) {
            load_stage(sb, gs + 1, r0);
            asm volatile("cp.async.commit_group;" ::: "memory");
            asm volatile("cp.async.wait_group 1;" ::: "memory");
        } else {
            asm volatile("cp.async.wait_group 0;" ::: "memory");
        }
        __syncthreads();

        if ((gs & 31) == 0) {
#pragma unroll
            for (int mt = 0; mt < 2; mt++)
#pragma unroll
                for (int nt = 0; nt < 16; nt++)
#pragma unroll
                    for (int e = 0; e < 4; e++) acc[mt][nt][e] = 0.0f;
        }

        const uint32_t a_base = sb + buf * STAGE_SZ + SA;
        const uint32_t b_base = sb + buf * STAGE_SZ + SB + (warp_n + b_row_off) * STRIDE;
#pragma unroll
        for (int kh = 0; kh < 2; kh++) {
            const int kk = kh * 16;
            uint32_t ah[2][4], al[2][4];
#pragma unroll
            for (int mt = 0; mt < 2; mt++) {
                const uint32_t ra = a_base + (warp_m + mt * 16 + a_row_off) * STRIDE
                                  + (kk + a_k_off) * 2;
                ldsm4(ah[mt], ra);
                ldsm4(al[mt], ra + 10240);
            }
#pragma unroll
            for (int p = 0; p < 8; p++) {
                uint32_t bh[4], bl[4];
                const uint32_t rb = b_base + p * 16 * STRIDE + (kk + b_k_off) * 2;
                ldsm4(bh, rb);
                ldsm4(bl, rb + 20480);
#pragma unroll
                for (int mt = 0; mt < 2; mt++) {
                    mma16816(acc[mt][2 * p],     ah[mt], bh);
                    mma16816(acc[mt][2 * p],     ah[mt], bl);
                    mma16816(acc[mt][2 * p],     al[mt], bh);
                    mma16816(acc[mt][2 * p + 1], ah[mt], bh + 2);
                    mma16816(acc[mt][2 * p + 1], ah[mt], bl + 2);
                    mma16816(acc[mt][2 * p + 1], al[mt], bh + 2);
                }
            }
        }
        __syncthreads();

        if ((gs & 31) == 31) {
            const int oo = (gs >> 5) * NT + warp_n + (lane & 3) * 2;
#pragma unroll
            for (int mt = 0; mt < 2; mt++)
#pragma unroll
                for (int nt = 0; nt < 16; nt++) {
                    const int o0e = oo + nt * 8;
                    const float b0 = s_bias[o0e], b1 = s_bias[o0e + 1];
                    const float v0 = s_v[o0e],    v1 = s_v[o0e + 1];
                    const float* c = acc[mt][nt];
                    part[mt * 2 + 0] += ftanh(c[0] + b0) * v0 + ftanh(c[1] + b1) * v1;
                    part[mt * 2 + 1] += ftanh(c[2] + b0) * v0 + ftanh(c[3] + b1) * v1;
                }
        }
    }

    // reduce 4-lane groups sharing each row, then combine the 2 n-warps
#pragma unroll
    for (int i = 0; i < 4; i++) {
        float s = part[i];
        s += __shfl_xor_sync(0xFFFFFFFFu, s, 1);
        s += __shfl_xor_sync(0xFFFFFFFFu, s, 2);
        if ((lane & 3) == 0) {
            const int row = warp_m + (i >> 1) * 16 + (i & 1) * 8 + (lane >> 2);
            atomicAdd(&s_row[row], s);
        }
    }
    __syncthreads();
    if (tid < ROWS_CTA) g_logits[r0 + tid] = s_row[tid];
}

// ---------------- softmax over s per batch ----------------
__global__ void softmax_kernel(float* __restrict__ out) {
    __shared__ float red[256];
    const int b = blockIdx.x, tid = threadIdx.x;
    const float* lg = g_logits + (size_t)b * SDIM;
    float vals[8];
    float lmax = -1e30f;
#pragma unroll
    for (int i = 0; i < 8; i++) {
        vals[i] = lg[tid + i * 256];
        lmax = fmaxf(lmax, vals[i]);
    }
    red[tid] = lmax;
    __syncthreads();
    for (int s = 128; s > 0; s >>= 1) {
        if (tid < s) red[tid] = fmaxf(red[tid], red[tid + s]);
        __syncthreads();
    }
    lmax = red[0];
    __syncthreads();
    float lsum = 0.0f;
#pragma unroll
    for (int i = 0; i < 8; i++) {
        vals[i] = expf(vals[i] - lmax);
        lsum += vals[i];
    }
    red[tid] = lsum;
    __syncthreads();
    for (int s = 128; s > 0; s >>= 1) {
        if (tid < s) red[tid] += red[tid + s];
        __syncthreads();
    }
    const float inv = 1.0f / red[0];
#pragma unroll
    for (int i = 0; i < 8; i++)
        out[(size_t)b * SDIM + tid + i * 256] = vals[i] * inv;
}

// ---------------- launch ----------------
extern "C" void kernel_launch(void* const* d_in, const int* in_sizes, int n_in,
                              void* d_out, int out_size) {
    const float* hidden = (const float*)d_in[0];
    const float* enc    = (const float*)d_in[1];
    const float* W      = (const float*)d_in[2];
    const float* b_attn = (const float*)d_in[3];
    const float* v      = (const float*)d_in[4];
    float* out = (float*)d_out;

    cudaFuncSetAttribute(gemm_kernel, cudaFuncAttributeMaxDynamicSharedMemorySize, SMEM_TOTAL);
    prep_kernel<<<33408, 256>>>(enc, W, hidden, b_attn);
    gemm_kernel<<<RDIM / ROWS_CTA, 256, SMEM_TOTAL>>>(v);
    softmax_kernel<<<32, 256>>>(out);
}

// round 7
// speedup vs baseline: 3.3495x; 1.5105x over previous
#include <cuda_runtime.h>
#include <cuda_fp16.h>
#include <cstdint>

#define SDIM 2048
#define HDIM 1024
#define RDIM 65536

// ---- gemm tiling ----
#define ROWS_CTA 128
#define NT 256                 // o-cols per o-iter
#define GSTEPS 128             // 4 o-iters x 32 k-steps (BK=32)

// ---- smem layout (bytes). 80B padded rows (64B data + 16B pad) ----
#define STRIDE 80
#define SA_HI 0                // A_hi: 128 rows x 80B = 10240
#define SA_LO 10240            // A_lo: 10240
#define SB    20480            // B:    256 rows x 80B = 20480
#define STAGE_SZ 40960
#define SM_BIAS (2 * STAGE_SZ) // 81920
#define SM_V    (SM_BIAS + 4096)
#define SM_ROW  (SM_V + 4096)
#define SMEM_TOTAL (SM_ROW + 512)   // 90624

__device__ __align__(16) __half g_we_h[(size_t)HDIM * HDIM];  // We rounded to fp16 (2MB)
__device__ float g_bias[32 * HDIM];
__device__ float g_logits[RDIM];

// ---------------- helpers ----------------
__device__ __forceinline__ uint32_t smem_u32(const void* p) {
    uint32_t a;
    asm("{ .reg .u64 t; cvta.to.shared.u64 t, %1; cvt.u32.u64 %0, t; }" : "=r"(a) : "l"(p));
    return a;
}
__device__ __forceinline__ void cp16(uint32_t dst, const void* src) {
    asm volatile("cp.async.cg.shared.global [%0], [%1], 16;" :: "r"(dst), "l"(src) : "memory");
}
__device__ __forceinline__ void ldsm4(uint32_t* r, uint32_t a) {
    asm volatile("ldmatrix.sync.aligned.m8n8.x4.shared.b16 {%0,%1,%2,%3}, [%4];"
                 : "=r"(r[0]), "=r"(r[1]), "=r"(r[2]), "=r"(r[3]) : "r"(a));
}
__device__ __forceinline__ void mma16816(float* c, const uint32_t* a, const uint32_t* b) {
    asm volatile("mma.sync.aligned.m16n8k16.row.col.f32.f16.f16.f32 "
                 "{%0,%1,%2,%3}, {%4,%5,%6,%7}, {%8,%9}, {%0,%1,%2,%3};"
                 : "+f"(c[0]), "+f"(c[1]), "+f"(c[2]), "+f"(c[3])
                 : "r"(a[0]), "r"(a[1]), "r"(a[2]), "r"(a[3]), "r"(b[0]), "r"(b[1]));
}
// accurate fast tanh: sign(x)*(1 - 2/(e^{2|x|}+1)), 2 MUFU, ~1e-6 err
__device__ __forceinline__ float ftanh(float x) {
    float ax = fminf(fabsf(x), 12.0f);
    float e;
    asm("ex2.approx.f32 %0, %1;" : "=f"(e) : "f"(ax * 2.885390082f));
    float r;
    asm("rcp.approx.f32 %0, %1;" : "=f"(r) : "f"(e + 1.0f));
    return copysignf(fmaf(-2.0f, r, 1.0f), x);
}

// ---------------- prep: We -> fp16 (2MB) + bias GEMV ----------------
// blocks: [0,512) We convert, [512,640) bias
__global__ void __launch_bounds__(256) prep_kernel(const float* __restrict__ W,
                                                   const float* __restrict__ hidden,
                                                   const float* __restrict__ b_attn) {
    __shared__ float4 sh[HDIM / 4];
    const int bid = blockIdx.x, tid = threadIdx.x;
    if (bid < 512) {
        const size_t base = ((size_t)bid * 256 + tid) * 8;
        const int o = (int)(base >> 10), k = (int)(base & 1023);
        const float4* p = (const float4*)(W + (size_t)o * 2 * HDIM + HDIM + k);
        const float4 a = p[0], b = p[1];
        const float f[8] = {a.x, a.y, a.z, a.w, b.x, b.y, b.z, b.w};
        __half h[8];
#pragma unroll
        for (int i = 0; i < 8; i++) h[i] = __float2half_rn(f[i]);
        *(uint4*)(g_we_h + base) = *(const uint4*)h;
    } else {
        const int b2 = bid - 512;          // 0..127
        const int b = b2 & 31, ot = b2 >> 5;
        const float4* hv = (const float4*)(hidden + (size_t)b * HDIM);
        for (int i = tid; i < HDIM / 4; i += 256) sh[i] = hv[i];
        __syncthreads();
        const int o = ot * 256 + tid;
        const float4* wr = (const float4*)(W + (size_t)o * 2 * HDIM);
        float acc = b_attn[o];
#pragma unroll 8
        for (int i = 0; i < HDIM / 4; i++) {
            const float4 w = wr[i], h4 = sh[i];
            acc = fmaf(w.x, h4.x, acc);
            acc = fmaf(w.y, h4.y, acc);
            acc = fmaf(w.z, h4.z, acc);
            acc = fmaf(w.w, h4.w, acc);
        }
        g_bias[b * HDIM + o] = acc;
    }
}

// ---------------- gemm pieces ----------------
// A: thread (row = tid>>1, seg = tid&1) loads 16 fp32 of enc row
__device__ __forceinline__ void ldgA(float* af, const float* __restrict__ enc, int gs, int r0) {
    const int tid = threadIdx.x;
    const int row = tid >> 1, seg = tid & 1;
    const int k0 = (gs & 31) * 32;
    const float* p = enc + (size_t)(r0 + row) * HDIM + k0 + seg * 16;
#pragma unroll
    for (int i = 0; i < 4; i++)
        *(float4*)(af + i * 4) = *(const float4*)(p + i * 4);
}
__device__ __forceinline__ void stsA(const float* af, char* smem, int gs) {
    const int tid = threadIdx.x;
    const int row = tid >> 1, seg = tid & 1;
    __half hi[16], lo[16];
#pragma unroll
    for (int i = 0; i < 16; i++) {
        hi[i] = __float2half_rn(af[i]);
        lo[i] = __float2half_rn(af[i] - __half2float(hi[i]));
    }
    char* b = smem + (gs & 1) * STAGE_SZ + row * STRIDE + seg * 32;
    *(uint4*)(b + SA_HI)      = ((const uint4*)hi)[0];
    *(uint4*)(b + SA_HI + 16) = ((const uint4*)hi)[1];
    *(uint4*)(b + SA_LO)      = ((const uint4*)lo)[0];
    *(uint4*)(b + SA_LO + 16) = ((const uint4*)lo)[1];
}
__device__ __forceinline__ void cpB(uint32_t sb, int gs) {
    const int tid = threadIdx.x;
    const int k0 = (gs & 31) * 32, o0 = (gs >> 5) * NT;
    const uint32_t base = sb + (gs & 1) * STAGE_SZ + SB;
#pragma unroll
    for (int i = 0; i < 4; i++) {
        const int c = tid + i * 256;
        const int row = c >> 2, seg = c & 3;
        cp16(base + row * STRIDE + seg * 16,
             g_we_h + (size_t)(o0 + row) * HDIM + k0 + seg * 8);
    }
}

__global__ void __launch_bounds__(256, 1)
gemm_kernel(const float* __restrict__ enc, const float* __restrict__ v) {
    extern __shared__ char smem[];
    const uint32_t sb = smem_u32(smem);
    const int tid = threadIdx.x;
    const int lane = tid & 31, warp = tid >> 5;
    const int warp_m = (warp >> 1) * 32;      // 4 warps over M (2 mt of m16)
    const int warp_n = (warp & 1) * 128;      // 2 warps over N
    const int r0 = blockIdx.x * ROWS_CTA;
    const int bb = r0 >> 11;

    float* s_bias = (float*)(smem + SM_BIAS);
    float* s_v    = (float*)(smem + SM_V);
    float* s_row  = (float*)(smem + SM_ROW);
    for (int i = tid; i < HDIM; i += 256) {
        s_bias[i] = g_bias[bb * HDIM + i];
        s_v[i] = v[i];
    }
    if (tid < ROWS_CTA) s_row[tid] = 0.0f;

    // ldmatrix per-lane address components
    const int q = lane >> 3, rr = lane & 7;
    const int a_row_off = (q & 1) * 8 + rr;
    const int a_k_off   = (q >> 1) * 8;
    const int b_row_off = (q >> 1) * 8 + rr;
    const int b_k_off   = (q & 1) * 8;

    float af[16];
    // prologue: stage 0 fully loaded; stage 1 A in regs + B in flight
    ldgA(af, enc, 0, r0);
    cpB(sb, 0);
    asm volatile("cp.async.commit_group;" ::: "memory");
    stsA(af, smem, 0);
    ldgA(af, enc, 1, r0);
    cpB(sb, 1);
    asm volatile("cp.async.commit_group;" ::: "memory");

    float part[4] = {0.f, 0.f, 0.f, 0.f};
    float acc[2][16][4];

    for (int gs = 0; gs < GSTEPS; gs++) {
        const int buf = gs & 1;
        if (gs + 1 < GSTEPS)
            asm volatile("cp.async.wait_group 1;" ::: "memory");
        else
            asm volatile("cp.async.wait_group 0;" ::: "memory");
        __syncthreads();

        if ((gs & 31) == 0) {
#pragma unroll
            for (int mt = 0; mt < 2; mt++)
#pragma unroll
                for (int nt = 0; nt < 16; nt++)
#pragma unroll
                    for (int e = 0; e < 4; e++) acc[mt][nt][e] = 0.0f;
        }

        const uint32_t a_base = sb + buf * STAGE_SZ;
        const uint32_t b_base = sb + buf * STAGE_SZ + SB + (warp_n + b_row_off) * STRIDE;
#pragma unroll
        for (int kh = 0; kh < 2; kh++) {
            const int kk = kh * 16;
            uint32_t ah[2][4], al[2][4];
#pragma unroll
            for (int mt = 0; mt < 2; mt++) {
                const uint32_t ra = a_base + (warp_m + mt * 16 + a_row_off) * STRIDE
                                  + (kk + a_k_off) * 2;
                ldsm4(ah[mt], ra + SA_HI);
                ldsm4(al[mt], ra + SA_LO);
            }
#pragma unroll
            for (int p = 0; p < 8; p++) {
                uint32_t bh[4];
                const uint32_t rb = b_base + p * 16 * STRIDE + (kk + b_k_off) * 2;
                ldsm4(bh, rb);
#pragma unroll
                for (int mt = 0; mt < 2; mt++) {
                    mma16816(acc[mt][2 * p],     ah[mt], bh);
                    mma16816(acc[mt][2 * p],     al[mt], bh);
                    mma16816(acc[mt][2 * p + 1], ah[mt], bh + 2);
                    mma16816(acc[mt][2 * p + 1], al[mt], bh + 2);
                }
            }
        }
        __syncthreads();

        if ((gs & 31) == 31) {
            const int oo = (gs >> 5) * NT + warp_n + (lane & 3) * 2;
#pragma unroll
            for (int mt = 0; mt < 2; mt++)
#pragma unroll
                for (int nt = 0; nt < 16; nt++) {
                    const int o0e = oo + nt * 8;
                    const float b0 = s_bias[o0e], b1 = s_bias[o0e + 1];
                    const float v0 = s_v[o0e],    v1 = s_v[o0e + 1];
                    const float* c = acc[mt][nt];
                    part[mt * 2 + 0] += ftanh(c[0] + b0) * v0 + ftanh(c[1] + b1) * v1;
                    part[mt * 2 + 1] += ftanh(c[2] + b0) * v0 + ftanh(c[3] + b1) * v1;
                }
        }

        // pipeline: STS A(gs+1) from regs; prefetch A(gs+2) + B(gs+2)
        if (gs + 1 < GSTEPS) stsA(af, smem, gs + 1);
        if (gs + 2 < GSTEPS) {
            ldgA(af, enc, gs + 2, r0);
            cpB(sb, gs + 2);
        }
        asm volatile("cp.async.commit_group;" ::: "memory");
    }

    // reduce 4-lane groups sharing each row, then combine across n-warps
#pragma unroll
    for (int i = 0; i < 4; i++) {
        float s = part[i];
        s += __shfl_xor_sync(0xFFFFFFFFu, s, 1);
        s += __shfl_xor_sync(0xFFFFFFFFu, s, 2);
        if ((lane & 3) == 0) {
            const int row = warp_m + (i >> 1) * 16 + (i & 1) * 8 + (lane >> 2);
            atomicAdd(&s_row[row], s);
        }
    }
    __syncthreads();
    if (tid < ROWS_CTA) g_logits[r0 + tid] = s_row[tid];
}

// ---------------- softmax over s per batch ----------------
__global__ void softmax_kernel(float* __restrict__ out) {
    __shared__ float red[256];
    const int b = blockIdx.x, tid = threadIdx.x;
    const float* lg = g_logits + (size_t)b * SDIM;
    float vals[8];
    float lmax = -1e30f;
#pragma unroll
    for (int i = 0; i < 8; i++) {
        vals[i] = lg[tid + i * 256];
        lmax = fmaxf(lmax, vals[i]);
    }
    red[tid] = lmax;
    __syncthreads();
    for (int s = 128; s > 0; s >>= 1) {
        if (tid < s) red[tid] = fmaxf(red[tid], red[tid + s]);
        __syncthreads();
    }
    lmax = red[0];
    __syncthreads();
    float lsum = 0.0f;
#pragma unroll
    for (int i = 0; i < 8; i++) {
        vals[i] = expf(vals[i] - lmax);
        lsum += vals[i];
    }
    red[tid] = lsum;
    __syncthreads();
    for (int s = 128; s > 0; s >>= 1) {
        if (tid < s) red[tid] += red[tid + s];
        __syncthreads();
    }
    const float inv = 1.0f / red[0];
#pragma unroll
    for (int i = 0; i < 8; i++)
        out[(size_t)b * SDIM + tid + i * 256] = vals[i] * inv;
}

// ---------------- launch ----------------
extern "C" void kernel_launch(void* const* d_in, const int* in_sizes, int n_in,
                              void* d_out, int out_size) {
    const float* hidden = (const float*)d_in[0];
    const float* enc    = (const float*)d_in[1];
    const float* W      = (const float*)d_in[2];
    const float* b_attn = (const float*)d_in[3];
    const float* v      = (const float*)d_in[4];
    float* out = (float*)d_out;

    cudaFuncSetAttribute(gemm_kernel, cudaFuncAttributeMaxDynamicSharedMemorySize, SMEM_TOTAL);
    prep_kernel<<<640, 256>>>(W, hidden, b_attn);
    gemm_kernel<<<RDIM / ROWS_CTA, 256, SMEM_TOTAL>>>(enc, v);
    softmax_kernel<<<32, 256>>>(out);
}

// round 8
// speedup vs baseline: 4.9897x; 1.4897x over previous
#include <cuda_runtime.h>
#include <cuda_fp16.h>
#include <cstdint>

#define SDIM 2048
#define HDIM 1024
#define RDIM 65536

// ---- gemm tiling ----
#define ROWS_CTA 128
#define NT 256                 // o-cols per o-iter
#define GSTEPS 128             // 4 o-iters x 32 k-steps (BK=32)

// ---- smem layout (bytes). 80B padded rows (64B data + 16B pad) ----
#define STRIDE 80
#define SA    0                // A: 128 rows x 80B = 10240 (fp16)
#define SB    10240            // B: 256 rows x 80B = 20480 (fp16)
#define STAGE_SZ 30720
#define SM_BIAS (2 * STAGE_SZ) // 61440
#define SM_V    (SM_BIAS + 4096)
#define SM_ROW  (SM_V + 4096)
#define SMEM_TOTAL (SM_ROW + 512)   // 70144

__device__ __align__(16) __half g_we_h[(size_t)HDIM * HDIM];  // We rounded to fp16 (2MB)
__device__ float g_bias[32 * HDIM];
__device__ float g_logits[RDIM];

// ---------------- helpers ----------------
__device__ __forceinline__ uint32_t smem_u32(const void* p) {
    uint32_t a;
    asm("{ .reg .u64 t; cvta.to.shared.u64 t, %1; cvt.u32.u64 %0, t; }" : "=r"(a) : "l"(p));
    return a;
}
__device__ __forceinline__ void cp16(uint32_t dst, const void* src) {
    asm volatile("cp.async.cg.shared.global [%0], [%1], 16;" :: "r"(dst), "l"(src) : "memory");
}
__device__ __forceinline__ void ldsm4(uint32_t* r, uint32_t a) {
    asm volatile("ldmatrix.sync.aligned.m8n8.x4.shared.b16 {%0,%1,%2,%3}, [%4];"
                 : "=r"(r[0]), "=r"(r[1]), "=r"(r[2]), "=r"(r[3]) : "r"(a));
}
__device__ __forceinline__ void mma16816(float* c, const uint32_t* a, const uint32_t* b) {
    asm volatile("mma.sync.aligned.m16n8k16.row.col.f32.f16.f16.f32 "
                 "{%0,%1,%2,%3}, {%4,%5,%6,%7}, {%8,%9}, {%0,%1,%2,%3};"
                 : "+f"(c[0]), "+f"(c[1]), "+f"(c[2]), "+f"(c[3])
                 : "r"(a[0]), "r"(a[1]), "r"(a[2]), "r"(a[3]), "r"(b[0]), "r"(b[1]));
}
// accurate fast tanh: sign(x)*(1 - 2/(e^{2|x|}+1)), 2 MUFU, ~1e-6 err
__device__ __forceinline__ float ftanh(float x) {
    float ax = fminf(fabsf(x), 12.0f);
    float e;
    asm("ex2.approx.f32 %0, %1;" : "=f"(e) : "f"(ax * 2.885390082f));
    float r;
    asm("rcp.approx.f32 %0, %1;" : "=f"(r) : "f"(e + 1.0f));
    return copysignf(fmaf(-2.0f, r, 1.0f), x);
}

// ---------------- prep ----------------
// blocks [0,512): We -> fp16; blocks [512,544): bias GEMV tile (Wh read ONCE)
__global__ void __launch_bounds__(256) prep_kernel(const float* __restrict__ W,
                                                   const float* __restrict__ hidden,
                                                   const float* __restrict__ b_attn) {
    const int bid = blockIdx.x, tid = threadIdx.x;
    if (bid < 512) {
        const size_t base = ((size_t)bid * 256 + tid) * 8;
        const int o = (int)(base >> 10), k = (int)(base & 1023);
        const float4* p = (const float4*)(W + (size_t)o * 2 * HDIM + HDIM + k);
        const float4 a = p[0], b = p[1];
        const float f[8] = {a.x, a.y, a.z, a.w, b.x, b.y, b.z, b.w};
        __half h[8];
#pragma unroll
        for (int i = 0; i < 8; i++) h[i] = __float2half_rn(f[i]);
        *(uint4*)(g_we_h + base) = *(const uint4*)h;
    } else {
        // bias[b][o] = b_attn[o] + sum_k hidden[b][k] * W[o][k]
        // block handles o in [o0, o0+32) x all 32 b, k chunked by 128.
        __shared__ float sW[32 * 129];
        __shared__ float sH[32 * 129];
        const int o0 = (bid - 512) * 32;
        const int ol = tid & 31;          // local o
        const int b0 = tid >> 5;          // base b (0..7), +8j covers 32
        float acc[4] = {0.f, 0.f, 0.f, 0.f};
        for (int kc = 0; kc < 8; kc++) {
            const int k0 = kc * 128;
#pragma unroll
            for (int i = 0; i < 4; i++) {
                const int idx = tid + i * 256;          // 1024 float4 total
                const int row = idx >> 5, c4 = (idx & 31) * 4;
                const float4 w = *(const float4*)(W + (size_t)(o0 + row) * 2 * HDIM + k0 + c4);
                sW[row * 129 + c4 + 0] = w.x;
                sW[row * 129 + c4 + 1] = w.y;
                sW[row * 129 + c4 + 2] = w.z;
                sW[row * 129 + c4 + 3] = w.w;
                const float4 h = *(const float4*)(hidden + (size_t)row * HDIM + k0 + c4);
                sH[row * 129 + c4 + 0] = h.x;
                sH[row * 129 + c4 + 1] = h.y;
                sH[row * 129 + c4 + 2] = h.z;
                sH[row * 129 + c4 + 3] = h.w;
            }
            __syncthreads();
#pragma unroll 4
            for (int k = 0; k < 128; k++) {
                const float w = sW[ol * 129 + k];
#pragma unroll
                for (int j = 0; j < 4; j++)
                    acc[j] = fmaf(w, sH[(b0 + 8 * j) * 129 + k], acc[j]);
            }
            __syncthreads();
        }
        const float ba = b_attn[o0 + ol];
#pragma unroll
        for (int j = 0; j < 4; j++)
            g_bias[(b0 + 8 * j) * HDIM + o0 + ol] = acc[j] + ba;
    }
}

// ---------------- gemm pieces ----------------
// A: thread (row = tid>>1, seg = tid&1) loads 16 fp32 of enc row
__device__ __forceinline__ void ldgA(float* af, const float* __restrict__ enc, int gs, int r0) {
    const int tid = threadIdx.x;
    const int row = tid >> 1, seg = tid & 1;
    const int k0 = (gs & 31) * 32;
    const float* p = enc + (size_t)(r0 + row) * HDIM + k0 + seg * 16;
#pragma unroll
    for (int i = 0; i < 4; i++)
        *(float4*)(af + i * 4) = *(const float4*)(p + i * 4);
}
__device__ __forceinline__ void stsA(const float* af, char* smem, int gs) {
    const int tid = threadIdx.x;
    const int row = tid >> 1, seg = tid & 1;
    __half h[16];
#pragma unroll
    for (int i = 0; i < 16; i++) h[i] = __float2half_rn(af[i]);
    char* b = smem + (gs & 1) * STAGE_SZ + SA + row * STRIDE + seg * 32;
    *(uint4*)(b)      = ((const uint4*)h)[0];
    *(uint4*)(b + 16) = ((const uint4*)h)[1];
}
__device__ __forceinline__ void cpB(uint32_t sb, int gs) {
    const int tid = threadIdx.x;
    const int k0 = (gs & 31) * 32, o0 = (gs >> 5) * NT;
    const uint32_t base = sb + (gs & 1) * STAGE_SZ + SB;
#pragma unroll
    for (int i = 0; i < 4; i++) {
        const int c = tid + i * 256;
        const int row = c >> 2, seg = c & 3;
        cp16(base + row * STRIDE + seg * 16,
             g_we_h + (size_t)(o0 + row) * HDIM + k0 + seg * 8);
    }
}

__global__ void __launch_bounds__(256, 1)
gemm_kernel(const float* __restrict__ enc, const float* __restrict__ v) {
    extern __shared__ char smem[];
    const uint32_t sb = smem_u32(smem);
    const int tid = threadIdx.x;
    const int lane = tid & 31, warp = tid >> 5;
    const int warp_m = (warp >> 1) * 32;      // 4 warps over M (2 mt of m16)
    const int warp_n = (warp & 1) * 128;      // 2 warps over N
    const int r0 = blockIdx.x * ROWS_CTA;
    const int bb = r0 >> 11;

    float* s_bias = (float*)(smem + SM_BIAS);
    float* s_v    = (float*)(smem + SM_V);
    float* s_row  = (float*)(smem + SM_ROW);
    for (int i = tid; i < HDIM; i += 256) {
        s_bias[i] = g_bias[bb * HDIM + i];
        s_v[i] = v[i];
    }
    if (tid < ROWS_CTA) s_row[tid] = 0.0f;

    // ldmatrix per-lane address components
    const int q = lane >> 3, rr = lane & 7;
    const int a_row_off = (q & 1) * 8 + rr;
    const int a_k_off   = (q >> 1) * 8;
    const int b_row_off = (q >> 1) * 8 + rr;
    const int b_k_off   = (q & 1) * 8;

    float af[16];
    // prologue: stage 0 fully loaded; stage 1 A in regs + B in flight
    ldgA(af, enc, 0, r0);
    cpB(sb, 0);
    asm volatile("cp.async.commit_group;" ::: "memory");
    stsA(af, smem, 0);
    ldgA(af, enc, 1, r0);
    cpB(sb, 1);
    asm volatile("cp.async.commit_group;" ::: "memory");

    float part[4] = {0.f, 0.f, 0.f, 0.f};
    float acc[2][16][4];

    for (int gs = 0; gs < GSTEPS; gs++) {
        const int buf = gs & 1;
        if (gs + 1 < GSTEPS)
            asm volatile("cp.async.wait_group 1;" ::: "memory");
        else
            asm volatile("cp.async.wait_group 0;" ::: "memory");
        __syncthreads();

        if ((gs & 31) == 0) {
#pragma unroll
            for (int mt = 0; mt < 2; mt++)
#pragma unroll
                for (int nt = 0; nt < 16; nt++)
#pragma unroll
                    for (int e = 0; e < 4; e++) acc[mt][nt][e] = 0.0f;
        }

        const uint32_t a_base = sb + buf * STAGE_SZ + SA;
        const uint32_t b_base = sb + buf * STAGE_SZ + SB + (warp_n + b_row_off) * STRIDE;
#pragma unroll
        for (int kh = 0; kh < 2; kh++) {
            const int kk = kh * 16;
            uint32_t ah[2][4];
#pragma unroll
            for (int mt = 0; mt < 2; mt++) {
                const uint32_t ra = a_base + (warp_m + mt * 16 + a_row_off) * STRIDE
                                  + (kk + a_k_off) * 2;
                ldsm4(ah[mt], ra);
            }
#pragma unroll
            for (int p = 0; p < 8; p++) {
                uint32_t bh[4];
                const uint32_t rb = b_base + p * 16 * STRIDE + (kk + b_k_off) * 2;
                ldsm4(bh, rb);
#pragma unroll
                for (int mt = 0; mt < 2; mt++) {
                    mma16816(acc[mt][2 * p],     ah[mt], bh);
                    mma16816(acc[mt][2 * p + 1], ah[mt], bh + 2);
                }
            }
        }
        __syncthreads();

        if ((gs & 31) == 31) {
            const int oo = (gs >> 5) * NT + warp_n + (lane & 3) * 2;
#pragma unroll
            for (int mt = 0; mt < 2; mt++)
#pragma unroll
                for (int nt = 0; nt < 16; nt++) {
                    const int o0e = oo + nt * 8;
                    const float b0 = s_bias[o0e], b1 = s_bias[o0e + 1];
                    const float v0 = s_v[o0e],    v1 = s_v[o0e + 1];
                    const float* c = acc[mt][nt];
                    part[mt * 2 + 0] += ftanh(c[0] + b0) * v0 + ftanh(c[1] + b1) * v1;
                    part[mt * 2 + 1] += ftanh(c[2] + b0) * v0 + ftanh(c[3] + b1) * v1;
                }
        }

        // pipeline: STS A(gs+1) from regs; prefetch A(gs+2) + B(gs+2)
        if (gs + 1 < GSTEPS) stsA(af, smem, gs + 1);
        if (gs + 2 < GSTEPS) {
            ldgA(af, enc, gs + 2, r0);
            cpB(sb, gs + 2);
        }
        asm volatile("cp.async.commit_group;" ::: "memory");
    }

    // reduce 4-lane groups sharing each row, then combine across n-warps
#pragma unroll
    for (int i = 0; i < 4; i++) {
        float s = part[i];
        s += __shfl_xor_sync(0xFFFFFFFFu, s, 1);
        s += __shfl_xor_sync(0xFFFFFFFFu, s, 2);
        if ((lane & 3) == 0) {
            const int row = warp_m + (i >> 1) * 16 + (i & 1) * 8 + (lane >> 2);
            atomicAdd(&s_row[row], s);
        }
    }
    __syncthreads();
    if (tid < ROWS_CTA) g_logits[r0 + tid] = s_row[tid];
}

// ---------------- softmax over s per batch ----------------
__global__ void softmax_kernel(float* __restrict__ out) {
    __shared__ float red[256];
    const int b = blockIdx.x, tid = threadIdx.x;
    const float* lg = g_logits + (size_t)b * SDIM;
    float vals[8];
    float lmax = -1e30f;
#pragma unroll
    for (int i = 0; i < 8; i++) {
        vals[i] = lg[tid + i * 256];
        lmax = fmaxf(lmax, vals[i]);
    }
    red[tid] = lmax;
    __syncthreads();
    for (int s = 128; s > 0; s >>= 1) {
        if (tid < s) red[tid] = fmaxf(red[tid], red[tid + s]);
        __syncthreads();
    }
    lmax = red[0];
    __syncthreads();
    float lsum = 0.0f;
#pragma unroll
    for (int i = 0; i < 8; i++) {
        vals[i] = expf(vals[i] - lmax);
        lsum += vals[i];
    }
    red[tid] = lsum;
    __syncthreads();
    for (int s = 128; s > 0; s >>= 1) {
        if (tid < s) red[tid] += red[tid + s];
        __syncthreads();
    }
    const float inv = 1.0f / red[0];
#pragma unroll
    for (int i = 0; i < 8; i++)
        out[(size_t)b * SDIM + tid + i * 256] = vals[i] * inv;
}

// ---------------- launch ----------------
extern "C" void kernel_launch(void* const* d_in, const int* in_sizes, int n_in,
                              void* d_out, int out_size) {
    const float* hidden = (const float*)d_in[0];
    const float* enc    = (const float*)d_in[1];
    const float* W      = (const float*)d_in[2];
    const float* b_attn = (const float*)d_in[3];
    const float* v      = (const float*)d_in[4];
    float* out = (float*)d_out;

    cudaFuncSetAttribute(gemm_kernel, cudaFuncAttributeMaxDynamicSharedMemorySize, SMEM_TOTAL);
    prep_kernel<<<544, 256>>>(W, hidden, b_attn);
    gemm_kernel<<<RDIM / ROWS_CTA, 256, SMEM_TOTAL>>>(enc, v);
    softmax_kernel<<<32, 256>>>(out);
}

// round 10
// speedup vs baseline: 6.9671x; 1.3963x over previous
#include <cuda_runtime.h>
#include <cuda_fp16.h>
#include <cstdint>

#define SDIM 2048
#define HDIM 1024
#define RDIM 65536

// ---- gemm tiling ----
#define ROWS_CTA 64
#define NT 256                 // o-cols per o-iter
#define GSTEPS 128             // 4 o-iters x 32 k-steps (BK=32)

// ---- smem layout (bytes). 80B padded rows (64B data + 16B pad) ----
#define STRIDE 80
#define SA    0                // A: 64 rows x 80B = 5120 (fp16)
#define SB    5120             // B: 256 rows x 80B = 20480 (fp16)
#define STAGE_SZ 25600
#define NSTG 3
#define SM_BIAS (NSTG * STAGE_SZ)   // 76800
#define SM_V    (SM_BIAS + 4096)
#define SM_ROW  (SM_V + 4096)
#define SMEM_TOTAL (SM_ROW + 256)   // 85248

__device__ __align__(16) __half g_we_h[(size_t)HDIM * HDIM];  // We rounded to fp16 (2MB)
__device__ float g_bias[32 * HDIM];
__device__ float g_logits[RDIM];

// ---------------- helpers ----------------
__device__ __forceinline__ uint32_t smem_u32(const void* p) {
    uint32_t a;
    asm("{ .reg .u64 t; cvta.to.shared.u64 t, %1; cvt.u32.u64 %0, t; }" : "=r"(a) : "l"(p));
    return a;
}
__device__ __forceinline__ void cp16(uint32_t dst, const void* src) {
    asm volatile("cp.async.cg.shared.global [%0], [%1], 16;" :: "r"(dst), "l"(src) : "memory");
}
__device__ __forceinline__ void ldsm4(uint32_t* r, uint32_t a) {
    asm volatile("ldmatrix.sync.aligned.m8n8.x4.shared.b16 {%0,%1,%2,%3}, [%4];"
                 : "=r"(r[0]), "=r"(r[1]), "=r"(r[2]), "=r"(r[3]) : "r"(a));
}
__device__ __forceinline__ void mma16816(float* c, const uint32_t* a, const uint32_t* b) {
    asm volatile("mma.sync.aligned.m16n8k16.row.col.f32.f16.f16.f32 "
                 "{%0,%1,%2,%3}, {%4,%5,%6,%7}, {%8,%9}, {%0,%1,%2,%3};"
                 : "+f"(c[0]), "+f"(c[1]), "+f"(c[2]), "+f"(c[3])
                 : "r"(a[0]), "r"(a[1]), "r"(a[2]), "r"(a[3]), "r"(b[0]), "r"(b[1]));
}
// accurate fast tanh: sign(x)*(1 - 2/(e^{2|x|}+1)), 2 MUFU, ~1e-6 err
__device__ __forceinline__ float ftanh(float x) {
    float ax = fminf(fabsf(x), 12.0f);
    float e;
    asm("ex2.approx.f32 %0, %1;" : "=f"(e) : "f"(ax * 2.885390082f));
    float r;
    asm("rcp.approx.f32 %0, %1;" : "=f"(r) : "f"(e + 1.0f));
    return copysignf(fmaf(-2.0f, r, 1.0f), x);
}

// ---------------- prep ----------------
// blocks [0,512): We -> fp16; blocks [512,544): bias GEMV tile (Wh read ONCE)
__global__ void __launch_bounds__(256) prep_kernel(const float* __restrict__ W,
                                                   const float* __restrict__ hidden,
                                                   const float* __restrict__ b_attn) {
    const int bid = blockIdx.x, tid = threadIdx.x;
    if (bid < 512) {
        const size_t base = ((size_t)bid * 256 + tid) * 8;
        const int o = (int)(base >> 10), k = (int)(base & 1023);
        const float4* p = (const float4*)(W + (size_t)o * 2 * HDIM + HDIM + k);
        const float4 a = p[0], b = p[1];
        const float f[8] = {a.x, a.y, a.z, a.w, b.x, b.y, b.z, b.w};
        __half h[8];
#pragma unroll
        for (int i = 0; i < 8; i++) h[i] = __float2half_rn(f[i]);
        *(uint4*)(g_we_h + base) = *(const uint4*)h;
    } else {
        __shared__ float sW[32 * 129];
        __shared__ float sH[32 * 129];
        const int o0 = (bid - 512) * 32;
        const int ol = tid & 31;
        const int b0 = tid >> 5;
        float acc[4] = {0.f, 0.f, 0.f, 0.f};
        for (int kc = 0; kc < 8; kc++) {
            const int k0 = kc * 128;
#pragma unroll
            for (int i = 0; i < 4; i++) {
                const int idx = tid + i * 256;
                const int row = idx >> 5, c4 = (idx & 31) * 4;
                const float4 w = *(const float4*)(W + (size_t)(o0 + row) * 2 * HDIM + k0 + c4);
                sW[row * 129 + c4 + 0] = w.x;
                sW[row * 129 + c4 + 1] = w.y;
                sW[row * 129 + c4 + 2] = w.z;
                sW[row * 129 + c4 + 3] = w.w;
                const float4 h = *(const float4*)(hidden + (size_t)row * HDIM + k0 + c4);
                sH[row * 129 + c4 + 0] = h.x;
                sH[row * 129 + c4 + 1] = h.y;
                sH[row * 129 + c4 + 2] = h.z;
                sH[row * 129 + c4 + 3] = h.w;
            }
            __syncthreads();
#pragma unroll 4
            for (int k = 0; k < 128; k++) {
                const float w = sW[ol * 129 + k];
#pragma unroll
                for (int j = 0; j < 4; j++)
                    acc[j] = fmaf(w, sH[(b0 + 8 * j) * 129 + k], acc[j]);
            }
            __syncthreads();
        }
        const float ba = b_attn[o0 + ol];
#pragma unroll
        for (int j = 0; j < 4; j++)
            g_bias[(b0 + 8 * j) * HDIM + o0 + ol] = acc[j] + ba;
    }
}

// ---------------- gemm pieces ----------------
// A: thread (row = tid>>2, seg = tid&3) loads 8 fp32 of enc row
__device__ __forceinline__ void ldgA(float* af, const float* __restrict__ enc, int gs, int r0) {
    const int tid = threadIdx.x;
    const int row = tid >> 2, seg = tid & 3;
    const int k0 = (gs & 31) * 32;
    const float* p = enc + (size_t)(r0 + row) * HDIM + k0 + seg * 8;
    *(float4*)(af)     = *(const float4*)(p);
    *(float4*)(af + 4) = *(const float4*)(p + 4);
}
__device__ __forceinline__ void stsA(const float* af, char* smem, int gs) {
    const int tid = threadIdx.x;
    const int row = tid >> 2, seg = tid & 3;
    __half h[8];
#pragma unroll
    for (int i = 0; i < 8; i++) h[i] = __float2half_rn(af[i]);
    char* b = smem + (gs % NSTG) * STAGE_SZ + SA + row * STRIDE + seg * 16;
    *(uint4*)(b) = *(const uint4*)h;
}
__device__ __forceinline__ void cpB(uint32_t sb, int gs) {
    const int tid = threadIdx.x;
    const int k0 = (gs & 31) * 32, o0 = (gs >> 5) * NT;
    const uint32_t base = sb + (gs % NSTG) * STAGE_SZ + SB;
#pragma unroll
    for (int i = 0; i < 4; i++) {
        const int c = tid + i * 256;
        const int row = c >> 2, seg = c & 3;
        cp16(base + row * STRIDE + seg * 16,
             g_we_h + (size_t)(o0 + row) * HDIM + k0 + seg * 8);
    }
}

__global__ void __launch_bounds__(256, 2)
gemm_kernel(const float* __restrict__ enc, const float* __restrict__ v) {
    extern __shared__ char smem[];
    const uint32_t sb = smem_u32(smem);
    const int tid = threadIdx.x;
    const int lane = tid & 31, warp = tid >> 5;
    const int warp_m = (warp >> 2) * 32;      // 2 warps over M (2 mt of m16)
    const int warp_n = (warp & 3) * 64;       // 4 warps over N
    const int r0 = blockIdx.x * ROWS_CTA;
    const int bb = r0 >> 11;

    float* s_bias = (float*)(smem + SM_BIAS);
    float* s_v    = (float*)(smem + SM_V);
    float* s_row  = (float*)(smem + SM_ROW);
    for (int i = tid; i < HDIM; i += 256) {
        s_bias[i] = g_bias[bb * HDIM + i];
        s_v[i] = v[i];
    }
    if (tid < ROWS_CTA) s_row[tid] = 0.0f;

    // ldmatrix per-lane address components
    const int q = lane >> 3, rr = lane & 7;
    const int a_row_off = (q & 1) * 8 + rr;
    const int a_k_off   = (q >> 1) * 8;
    const int b_row_off = (q >> 1) * 8 + rr;
    const int b_k_off   = (q & 1) * 8;

    float af[8];
    // prologue: stages 0,1 fully in flight; A(2) in regs
    ldgA(af, enc, 0, r0);
    stsA(af, smem, 0);
    ldgA(af, enc, 1, r0);
    stsA(af, smem, 1);
    cpB(sb, 0);
    asm volatile("cp.async.commit_group;" ::: "memory");
    cpB(sb, 1);
    asm volatile("cp.async.commit_group;" ::: "memory");
    ldgA(af, enc, 2, r0);

    float part[4] = {0.f, 0.f, 0.f, 0.f};
    float acc[2][8][4];

    for (int gs = 0; gs < GSTEPS; gs++) {
        asm volatile("cp.async.wait_group 1;" ::: "memory");
        __syncthreads();

        // issue next-stage traffic before compute (single sync per stage)
        if (gs + 2 < GSTEPS) stsA(af, smem, gs + 2);
        if (gs + 3 < GSTEPS) ldgA(af, enc, gs + 3, r0);
        if (gs + 2 < GSTEPS) cpB(sb, gs + 2);
        asm volatile("cp.async.commit_group;" ::: "memory");

        if ((gs & 31) == 0) {
#pragma unroll
            for (int mt = 0; mt < 2; mt++)
#pragma unroll
                for (int nt = 0; nt < 8; nt++)
#pragma unroll
                    for (int e = 0; e < 4; e++) acc[mt][nt][e] = 0.0f;
        }

        const uint32_t stg = sb + (uint32_t)(gs % NSTG) * STAGE_SZ;
        const uint32_t a_base = stg + SA;
        const uint32_t b_base = stg + SB + (warp_n + b_row_off) * STRIDE;
#pragma unroll
        for (int kh = 0; kh < 2; kh++) {
            const int kk = kh * 16;
            uint32_t ah[2][4];
#pragma unroll
            for (int mt = 0; mt < 2; mt++) {
                const uint32_t ra = a_base + (warp_m + mt * 16 + a_row_off) * STRIDE
                                  + (kk + a_k_off) * 2;
                ldsm4(ah[mt], ra);
            }
#pragma unroll
            for (int p = 0; p < 4; p++) {
                uint32_t bh[4];
                const uint32_t rb = b_base + p * 16 * STRIDE + (kk + b_k_off) * 2;
                ldsm4(bh, rb);
#pragma unroll
                for (int mt = 0; mt < 2; mt++) {
                    mma16816(acc[mt][2 * p],     ah[mt], bh);
                    mma16816(acc[mt][2 * p + 1], ah[mt], bh + 2);
                }
            }
        }

        if ((gs & 31) == 31) {
            const int oo = (gs >> 5) * NT + warp_n + (lane & 3) * 2;
#pragma unroll
            for (int mt = 0; mt < 2; mt++)
#pragma unroll
                for (int nt = 0; nt < 8; nt++) {
                    const int o0e = oo + nt * 8;
                    const float b0 = s_bias[o0e], b1 = s_bias[o0e + 1];
                    const float v0 = s_v[o0e],    v1 = s_v[o0e + 1];
                    const float* c = acc[mt][nt];
                    part[mt * 2 + 0] += ftanh(c[0] + b0) * v0 + ftanh(c[1] + b1) * v1;
                    part[mt * 2 + 1] += ftanh(c[2] + b0) * v0 + ftanh(c[3] + b1) * v1;
                }
        }
    }

    // reduce 4-lane groups sharing each row, then combine across n-warps
#pragma unroll
    for (int i = 0; i < 4; i++) {
        float s = part[i];
        s += __shfl_xor_sync(0xFFFFFFFFu, s, 1);
        s += __shfl_xor_sync(0xFFFFFFFFu, s, 2);
        if ((lane & 3) == 0) {
            const int row = warp_m + (i >> 1) * 16 + (i & 1) * 8 + (lane >> 2);
            atomicAdd(&s_row[row], s);
        }
    }
    __syncthreads();
    if (tid < ROWS_CTA) g_logits[r0 + tid] = s_row[tid];
}

// ---------------- softmax over s per batch ----------------
__global__ void softmax_kernel(float* __restrict__ out) {
    __shared__ float red[256];
    const int b = blockIdx.x, tid = threadIdx.x;
    const float* lg = g_logits + (size_t)b * SDIM;
    float vals[8];
    float lmax = -1e30f;
#pragma unroll
    for (int i = 0; i < 8; i++) {
        vals[i] = lg[tid + i * 256];
        lmax = fmaxf(lmax, vals[i]);
    }
    red[tid] = lmax;
    __syncthreads();
    for (int s = 128; s > 0; s >>= 1) {
        if (tid < s) red[tid] = fmaxf(red[tid], red[tid + s]);
        __syncthreads();
    }
    lmax = red[0];
    __syncthreads();
    float lsum = 0.0f;
#pragma unroll
    for (int i = 0; i < 8; i++) {
        vals[i] = expf(vals[i] - lmax);
        lsum += vals[i];
    }
    red[tid] = lsum;
    __syncthreads();
    for (int s = 128; s > 0; s >>= 1) {
        if (tid < s) red[tid] += red[tid + s];
        __syncthreads();
    }
    const float inv = 1.0f / red[0];
#pragma unroll
    for (int i = 0; i < 8; i++)
        out[(size_t)b * SDIM + tid + i * 256] = vals[i] * inv;
}

// ---------------- launch ----------------
extern "C" void kernel_launch(void* const* d_in, const int* in_sizes, int n_in,
                              void* d_out, int out_size) {
    const float* hidden = (const float*)d_in[0];
    const float* enc    = (const float*)d_in[1];
    const float* W      = (const float*)d_in[2];
    const float* b_attn = (const float*)d_in[3];
    const float* v      = (const float*)d_in[4];
    float* out = (float*)d_out;

    cudaFuncSetAttribute(gemm_kernel, cudaFuncAttributeMaxDynamicSharedMemorySize, SMEM_TOTAL);
    prep_kernel<<<544, 256>>>(W, hidden, b_attn);
    gemm_kernel<<<RDIM / ROWS_CTA, 256, SMEM_TOTAL>>>(enc, v);
    softmax_kernel<<<32, 256>>>(out);
}